// round 1
// baseline (speedup 1.0000x reference)
#include <cuda_runtime.h>

// B=16384, N=100000, D=128, F1=64, F2=32
// y[b] = dot(emb[x[b]], v) + Wo[F2 + x[b]] + c
//   u = W2^T @ Wo[0:32]  (64)
//   v = W1^T @ u         (128)
//   c = b1.u + b2.wo + bo

__device__ float g_v[128];
__device__ float g_c;

__global__ void wdl_prep_kernel(const float* __restrict__ W1,
                                const float* __restrict__ b1,
                                const float* __restrict__ W2,
                                const float* __restrict__ b2,
                                const float* __restrict__ Wo,
                                const float* __restrict__ bo) {
    __shared__ float u[64];
    int t = threadIdx.x;  // 128 threads
    if (t < 64) {
        float s = 0.f;
        #pragma unroll
        for (int k = 0; k < 32; k++) s += W2[k * 64 + t] * Wo[k];
        u[t] = s;
    }
    __syncthreads();
    float s = 0.f;
    #pragma unroll
    for (int j = 0; j < 64; j++) s += W1[j * 128 + t] * u[j];
    g_v[t] = s;
    if (t == 0) {
        float c = bo[0];
        #pragma unroll
        for (int j = 0; j < 64; j++) c += b1[j] * u[j];
        #pragma unroll
        for (int k = 0; k < 32; k++) c += b2[k] * Wo[k];
        g_c = c;
    }
}

// One warp per batch row: 32 lanes x float4 = 512B coalesced row load.
__global__ void __launch_bounds__(256) wdl_main_kernel(
    const int* __restrict__ x,
    const float* __restrict__ emb,
    const float* __restrict__ Wo,
    float* __restrict__ out) {
    __shared__ float4 sv[32];
    if (threadIdx.x < 32)
        sv[threadIdx.x] = reinterpret_cast<const float4*>(g_v)[threadIdx.x];
    __syncthreads();

    int lane = threadIdx.x & 31;
    int warp = threadIdx.x >> 5;
    int row = blockIdx.x * 8 + warp;  // grid sized exactly: 16384/8

    int idx = x[row];
    const float4* e = reinterpret_cast<const float4*>(emb) + (long)idx * 32;
    float4 a = e[lane];
    float4 b = sv[lane];
    float s = a.x * b.x + a.y * b.y + a.z * b.z + a.w * b.w;

    #pragma unroll
    for (int off = 16; off; off >>= 1)
        s += __shfl_xor_sync(0xffffffff, s, off);

    if (lane == 0)
        out[row] = s + __ldg(&Wo[32 + idx]) + g_c;
}

extern "C" void kernel_launch(void* const* d_in, const int* in_sizes, int n_in,
                              void* d_out, int out_size) {
    const int*   x   = (const int*)d_in[0];
    const float* emb = (const float*)d_in[1];
    const float* W1  = (const float*)d_in[2];
    const float* b1  = (const float*)d_in[3];
    const float* W2  = (const float*)d_in[4];
    const float* b2  = (const float*)d_in[5];
    const float* Wo  = (const float*)d_in[6];
    const float* bo  = (const float*)d_in[7];
    float* out = (float*)d_out;

    const int B = in_sizes[0];  // 16384

    wdl_prep_kernel<<<1, 128>>>(W1, b1, W2, b2, Wo, bo);
    wdl_main_kernel<<<B / 8, 256>>>(x, emb, Wo, out);
}

// round 3
// speedup vs baseline: 1.0239x; 1.0239x over previous
#include <cuda_runtime.h>

// B=16384, N=100000, D=128, F1=64, F2=32
// y[b] = dot(emb[x[b]], v) + Wo[F2 + x[b]] + c
//   u = W2^T @ Wo[0:32]  (64)
//   v = W1^T @ u         (128)
//   c = b1.u + b2.wo + bo
// v/c recomputed redundantly per block (40KB of weights, L1/L2-resident)
// to keep a single launch with zero inter-block dependencies.

#define THREADS 512
#define ROWS_PER_WARP 4
#define ROWS_PER_BLOCK (ROWS_PER_WARP * (THREADS / 32))  // 64

__global__ void __launch_bounds__(THREADS) wdl_fused_kernel(
    const int*   __restrict__ x,
    const float* __restrict__ emb,
    const float* __restrict__ W1,
    const float* __restrict__ b1,
    const float* __restrict__ W2,
    const float* __restrict__ b2,
    const float* __restrict__ Wo,
    const float* __restrict__ bo,
    float* __restrict__ out) {
    __shared__ float  su[64];
    __shared__ float4 sv[32];
    __shared__ float  sc;

    int t    = threadIdx.x;
    int lane = t & 31;
    int warp = t >> 5;
    int base = blockIdx.x * ROWS_PER_BLOCK + warp * ROWS_PER_WARP;

    // ---- issue the random gathers FIRST (4 independent rows per warp) ----
    int idxl = 0;
    if (lane < ROWS_PER_WARP) idxl = x[base + lane];
    int i0 = __shfl_sync(0xffffffff, idxl, 0);
    int i1 = __shfl_sync(0xffffffff, idxl, 1);
    int i2 = __shfl_sync(0xffffffff, idxl, 2);
    int i3 = __shfl_sync(0xffffffff, idxl, 3);

    const float4* E = reinterpret_cast<const float4*>(emb);
    float4 a0 = E[(long)i0 * 32 + lane];
    float4 a1 = E[(long)i1 * 32 + lane];
    float4 a2 = E[(long)i2 * 32 + lane];
    float4 a3 = E[(long)i3 * 32 + lane];
    float  wol = 0.f;
    if (lane < ROWS_PER_WARP) wol = Wo[32 + idxl];

    // ---- per-block recompute of u, v, c (overlaps the gathers above) ----
    if (t < 64) {
        float s = 0.f;
        #pragma unroll
        for (int k = 0; k < 32; k++) s += W2[k * 64 + t] * Wo[k];
        su[t] = s;
    }
    __syncthreads();
    if (t < 128) {
        float s = 0.f;
        #pragma unroll
        for (int j = 0; j < 64; j++) s += W1[j * 128 + t] * su[j];
        reinterpret_cast<float*>(sv)[t] = s;
    }
    if (t == 0) {
        float c = bo[0];
        #pragma unroll
        for (int j = 0; j < 64; j++) c += b1[j] * su[j];
        #pragma unroll
        for (int k = 0; k < 32; k++) c += b2[k] * Wo[k];
        sc = c;
    }
    __syncthreads();

    // ---- dot + reduce + store ----
    float4 b = sv[lane];
    float  c = sc;

    float s0 = a0.x * b.x + a0.y * b.y + a0.z * b.z + a0.w * b.w;
    float s1 = a1.x * b.x + a1.y * b.y + a1.z * b.z + a1.w * b.w;
    float s2 = a2.x * b.x + a2.y * b.y + a2.z * b.z + a2.w * b.w;
    float s3 = a3.x * b.x + a3.y * b.y + a3.z * b.z + a3.w * b.w;

    #pragma unroll
    for (int off = 16; off; off >>= 1) {
        s0 += __shfl_xor_sync(0xffffffff, s0, off);
        s1 += __shfl_xor_sync(0xffffffff, s1, off);
        s2 += __shfl_xor_sync(0xffffffff, s2, off);
        s3 += __shfl_xor_sync(0xffffffff, s3, off);
    }

    if (lane < ROWS_PER_WARP) {
        float sv_ = (lane == 0) ? s0 : (lane == 1) ? s1 : (lane == 2) ? s2 : s3;
        out[base + lane] = sv_ + wol + c;
    }
}

extern "C" void kernel_launch(void* const* d_in, const int* in_sizes, int n_in,
                              void* d_out, int out_size) {
    const int*   x   = (const int*)d_in[0];
    const float* emb = (const float*)d_in[1];
    const float* W1  = (const float*)d_in[2];
    const float* b1  = (const float*)d_in[3];
    const float* W2  = (const float*)d_in[4];
    const float* b2  = (const float*)d_in[5];
    const float* Wo  = (const float*)d_in[6];
    const float* bo  = (const float*)d_in[7];
    float* out = (float*)d_out;

    const int B = in_sizes[0];  // 16384
    wdl_fused_kernel<<<B / ROWS_PER_BLOCK, THREADS>>>(x, emb, W1, b1, W2, b2, Wo, bo, out);
}